// round 15
// baseline (speedup 1.0000x reference)
#include <cuda_runtime.h>
#include <cstdint>
#include <math.h>

#define THREADS 256
#define NCELL 2048

// Tables computed once per replay by the setup kernel
__device__ float  g_A[48];          // softmax(A_param), rows padded to 8
__device__ float4 g_cell[NCELL];    // cell -> (a, b, dA, t); a=NaN => multi-knot fallback
__device__ float  g_st[32];         // sorted knots     (multi-knot fallback)
__device__ float  g_sdA[32];        // slope deltas     (multi-knot fallback)
__device__ float2 g_base;           // (a0, c0) leftmost segment

// Deterministic monotone cell index — MUST be bit-identical in setup & main.
__device__ __forceinline__ int cell_of(float y) {
    float d = 0.1f + fabsf(y);
    float r;
    asm("rcp.approx.f32 %0, %1;" : "=f"(r) : "f"(d));
    float g = y * r;                       // in (-1, 1)
    float fi = fmaf(g, 1024.f, 1024.f);    // in (0, 2048)
    fi = fmaxf(fi, 0.f);
    int ci = (int)fi;
    return min(ci, NCELL - 1);
}

__global__ void setup_kernel(const float* __restrict__ A_param,
                             const float* __restrict__ W1,
                             const float* __restrict__ b1,
                             const float* __restrict__ W2,
                             const float* __restrict__ b2)
{
    __shared__ float st[32], sdA[32], sdC_s[32];
    __shared__ float aa[33], cc[33];
    __shared__ int   kc[32];               // cell index of each sorted knot
    const int tid = threadIdx.x;           // 256 threads

    if (tid < 32) {
        float w1 = W1[tid], bb = b1[tid], w2 = W2[tid];
        float t, dA, dC, pc, qc;
        if (w1 > 0.f)      { t = -bb / w1; dA =  w1 * w2; dC =  bb * w2; pc = 0.f;     qc = 0.f; }
        else if (w1 < 0.f) { t = -bb / w1; dA = -(w1*w2); dC = -(bb*w2); pc = w1 * w2; qc = bb * w2; }
        else               { t = 1e30f;    dA = 0.f;      dC = 0.f;      pc = 0.f;     qc = fmaxf(bb, 0.f) * w2; }

        // base segment (y -> -inf): butterfly reduce
        float a0 = pc, c0 = qc;
        #pragma unroll
        for (int o = 16; o > 0; o >>= 1) {
            a0 += __shfl_xor_sync(0xFFFFFFFFu, a0, o);
            c0 += __shfl_xor_sync(0xFFFFFFFFu, c0, o);
        }
        c0 += b2[0];

        // stable rank-sort via shuffles
        int r = 0;
        #pragma unroll
        for (int j = 0; j < 32; ++j) {
            float tj = __shfl_sync(0xFFFFFFFFu, t, j);
            r += (tj < t || (tj == t && j < tid)) ? 1 : 0;
        }
        st[r] = t; sdA[r] = dA; sdC_s[r] = dC;
        __syncwarp();

        // inclusive scans of sorted (dA, dC)
        float da = sdA[tid], dc = sdC_s[tid];
        #pragma unroll
        for (int o = 1; o < 32; o <<= 1) {
            float va = __shfl_up_sync(0xFFFFFFFFu, da, o);
            float vc = __shfl_up_sync(0xFFFFFFFFu, dc, o);
            if (tid >= o) { da += va; dc += vc; }
        }
        aa[tid + 1] = a0 + da;
        cc[tid + 1] = c0 + dc;
        if (tid == 0) { aa[0] = a0; cc[0] = c0; g_base = make_float2(a0, c0); }
        __syncwarp();
        g_st[tid]  = st[tid];
        g_sdA[tid] = sdA[tid];
        kc[tid]    = cell_of(st[tid]);     // nondecreasing (st sorted, cell_of monotone)
    }

    // softmax rows of A_param
    if (tid < 6) {
        float v[6];
        float mx = -3.4e38f;
        #pragma unroll
        for (int n = 0; n < 6; ++n) { v[n] = A_param[tid * 6 + n]; mx = fmaxf(mx, v[n]); }
        float s = 0.f;
        #pragma unroll
        for (int n = 0; n < 6; ++n) { v[n] = expf(v[n] - mx); s += v[n]; }
        float inv = 1.f / s;
        #pragma unroll
        for (int n = 0; n < 6; ++n) g_A[tid * 8 + n] = v[n] * inv;
        g_A[tid * 8 + 6] = 0.f;
        g_A[tid * 8 + 7] = 0.f;
    }
    __syncthreads();

    // fill the cell table (integer compares against precomputed knot cells)
    for (int i = tid; i < NCELL; i += THREADS) {
        int n = 0, j = -1, cnt = 0;
        #pragma unroll
        for (int k = 0; k < 32; ++k) {
            int ck = kc[k];
            if (ck < i) ++n;
            else if (ck == i) { if (cnt == 0) j = k; ++cnt; }
        }
        float4 e;
        if (cnt == 0)      e = make_float4(aa[n], cc[n], 0.f, 0.f);
        else if (cnt == 1) e = make_float4(aa[n], cc[n], sdA[j], st[j]);
        else               e = make_float4(__int_as_float(0x7FC00000), 0.f, 0.f, 0.f);
        g_cell[i] = e;
    }
}

__global__ void __launch_bounds__(THREADS, 4) graphres_main(
    const float4* __restrict__ x,
    float4* __restrict__ out,
    int nvec4)
{
    __shared__ float4 sCell[NCELL];     // 32 KB, divergent LDS.128, branchless eval
    __shared__ float  sSt[32], sdA[32]; // ultra-rare multi-knot fallback
    __shared__ float  sA[48];
    __shared__ float2 sBase;

    const int tid = threadIdx.x;

    // table copy: 2048 float4 -> 8 LDG.128/STS.128 per thread
    #pragma unroll
    for (int i = 0; i < 8; ++i)
        sCell[tid + i * THREADS] = g_cell[tid + i * THREADS];
    if (tid < 48) sA[tid] = g_A[tid];
    if (tid < 32) {
        sSt[tid] = g_st[tid];
        sdA[tid] = g_sdA[tid];
    }
    if (tid == 0) sBase = g_base;
    __syncthreads();

    const uint32_t aBase = (uint32_t)__cvta_generic_to_shared(sA);
    const uint32_t cBase = (uint32_t)__cvta_generic_to_shared(sCell);

    const int gt = blockIdx.x * THREADS + tid;
    const int b0 = gt * 3;                 // 3 float4 = 2 rows of 6
    if (b0 + 3 > nvec4) return;

    float4 v0 = x[b0 + 0];
    float4 v1 = x[b0 + 1];
    float4 v2 = x[b0 + 2];
    float xr[12] = { v0.x, v0.y, v0.z, v0.w,
                     v1.x, v1.y, v1.z, v1.w,
                     v2.x, v2.y, v2.z, v2.w };

    #pragma unroll
    for (int r = 0; r < 2; ++r) {
        float* xx = xr + r * 6;
        float yv[6];

        // matvec y = A @ x_row (A rows streamed from smem)
        #pragma unroll
        for (int m = 0; m < 6; ++m) {
            float a0, a1, a2, a3, a4, a5;
            uint32_t aaddr = aBase + (uint32_t)(m * 32);
            asm volatile("ld.shared.v4.f32 {%0,%1,%2,%3},[%4];"
                         : "=f"(a0), "=f"(a1), "=f"(a2), "=f"(a3) : "r"(aaddr));
            asm volatile("ld.shared.v2.f32 {%0,%1},[%2];"
                         : "=f"(a4), "=f"(a5) : "r"(aaddr + 16u));
            float pa = a0 * xx[0];
            float pb = a1 * xx[1];
            pa = fmaf(a2, xx[2], pa);
            pb = fmaf(a3, xx[3], pb);
            pa = fmaf(a4, xx[4], pa);
            pb = fmaf(a5, xx[5], pb);
            yv[m] = pa + pb;
        }

        // O(1) branchless resolve: one divergent LDS.128, relu-fold eval.
        // Zero-knot cells have dA=0 so the fold is a no-op — same code path.
        #pragma unroll
        for (int e = 0; e < 6; ++e) {
            float y = yv[e];
            int ci = cell_of(y);
            float ca, cb, cd, ct;
            asm volatile("ld.shared.v4.f32 {%0,%1,%2,%3},[%4];"
                         : "=f"(ca), "=f"(cb), "=f"(cd), "=f"(ct)
                         : "r"(cBase + ((uint32_t)ci << 4)));
            float fr = fmaf(cd, fmaxf(y - ct, 0.f), fmaf(ca, y, cb));
            if (__builtin_expect(!(ca == ca), 0)) {
                // exact direct sum (cell holds >=2 knots; ~0.3% of warps)
                float2 bs = sBase;
                float acc = fmaf(bs.x, y, bs.y);
                #pragma unroll 4
                for (int k = 0; k < 32; ++k)
                    acc = fmaf(sdA[k], fmaxf(y - sSt[k], 0.f), acc);
                fr = acc;
            }
            xx[e] = fr + xx[e];
        }
    }

    out[b0 + 0] = make_float4(xr[0], xr[1], xr[2],  xr[3]);
    out[b0 + 1] = make_float4(xr[4], xr[5], xr[6],  xr[7]);
    out[b0 + 2] = make_float4(xr[8], xr[9], xr[10], xr[11]);
}

extern "C" void kernel_launch(void* const* d_in, const int* in_sizes, int n_in,
                              void* d_out, int out_size)
{
    const float* x  = (const float*)d_in[0];
    const float* Ap = (const float*)d_in[1];
    const float* W1 = (const float*)d_in[2];
    const float* b1 = (const float*)d_in[3];
    const float* W2 = (const float*)d_in[4];
    const float* b2 = (const float*)d_in[5];
    float* out = (float*)d_out;

    int nvec4 = out_size / 4;                       // total float4s (B*N/4)
    int threads_total = (nvec4 + 2) / 3;            // 3 float4 per thread
    int grid = (threads_total + THREADS - 1) / THREADS;

    setup_kernel<<<1, THREADS>>>(Ap, W1, b1, W2, b2);
    graphres_main<<<grid, THREADS>>>((const float4*)x, (float4*)out, nvec4);
}

// round 16
// speedup vs baseline: 1.1656x; 1.1656x over previous
#include <cuda_runtime.h>
#include <cstdint>
#include <math.h>

#define THREADS 256
#define NCELL 2048

// Tables computed once per replay by the setup kernel
__device__ float  g_A[48];          // softmax(A_param), rows padded to 8
__device__ float2 g_cell[NCELL];    // cell -> (a, b); a=NaN => b=bitcast(knot idx | 64)
__device__ float4 g_knot[32];       // knot j -> (a, b, dA, t) for its cell
__device__ float  g_st[32];         // sorted knots     (multi-knot fallback)
__device__ float  g_sdA[32];        // slope deltas     (multi-knot fallback)
__device__ float2 g_base;           // (a0, c0) leftmost segment

// Deterministic monotone cell index — MUST be bit-identical in setup & main.
__device__ __forceinline__ int cell_of(float y) {
    float d = 0.1f + fabsf(y);
    float r;
    asm("rcp.approx.f32 %0, %1;" : "=f"(r) : "f"(d));
    float g = y * r;                       // in (-1, 1)
    float fi = fmaf(g, 1024.f, 1024.f);    // in (0, 2048)
    fi = fmaxf(fi, 0.f);
    int ci = (int)fi;
    return min(ci, NCELL - 1);
}

__global__ void setup_kernel(const float* __restrict__ A_param,
                             const float* __restrict__ W1,
                             const float* __restrict__ b1,
                             const float* __restrict__ W2,
                             const float* __restrict__ b2)
{
    __shared__ float st[32], sdA[32], sdC_s[32];
    __shared__ float aa[33], cc[33];
    __shared__ int   kc[32];               // cell index of each sorted knot
    const int tid = threadIdx.x;           // 256 threads

    if (tid < 32) {
        float w1 = W1[tid], bb = b1[tid], w2 = W2[tid];
        float t, dA, dC, pc, qc;
        if (w1 > 0.f)      { t = -bb / w1; dA =  w1 * w2; dC =  bb * w2; pc = 0.f;     qc = 0.f; }
        else if (w1 < 0.f) { t = -bb / w1; dA = -(w1*w2); dC = -(bb*w2); pc = w1 * w2; qc = bb * w2; }
        else               { t = 1e30f;    dA = 0.f;      dC = 0.f;      pc = 0.f;     qc = fmaxf(bb, 0.f) * w2; }

        // base segment (y -> -inf): butterfly reduce
        float a0 = pc, c0 = qc;
        #pragma unroll
        for (int o = 16; o > 0; o >>= 1) {
            a0 += __shfl_xor_sync(0xFFFFFFFFu, a0, o);
            c0 += __shfl_xor_sync(0xFFFFFFFFu, c0, o);
        }
        c0 += b2[0];

        // stable rank-sort via shuffles
        int r = 0;
        #pragma unroll
        for (int j = 0; j < 32; ++j) {
            float tj = __shfl_sync(0xFFFFFFFFu, t, j);
            r += (tj < t || (tj == t && j < tid)) ? 1 : 0;
        }
        st[r] = t; sdA[r] = dA; sdC_s[r] = dC;
        __syncwarp();

        // inclusive scans of sorted (dA, dC)
        float da = sdA[tid], dc = sdC_s[tid];
        #pragma unroll
        for (int o = 1; o < 32; o <<= 1) {
            float va = __shfl_up_sync(0xFFFFFFFFu, da, o);
            float vc = __shfl_up_sync(0xFFFFFFFFu, dc, o);
            if (tid >= o) { da += va; dc += vc; }
        }
        aa[tid + 1] = a0 + da;
        cc[tid + 1] = c0 + dc;
        if (tid == 0) { aa[0] = a0; cc[0] = c0; g_base = make_float2(a0, c0); }
        __syncwarp();
        g_st[tid]  = st[tid];
        g_sdA[tid] = sdA[tid];
        kc[tid]    = cell_of(st[tid]);     // nondecreasing (st sorted, cell_of monotone)
        // knot-cell entry: segment left of knot j plus its relu fold
        g_knot[tid] = make_float4(aa[tid], cc[tid], sdA[tid], st[tid]);
    }

    // softmax rows of A_param
    if (tid < 6) {
        float v[6];
        float mx = -3.4e38f;
        #pragma unroll
        for (int n = 0; n < 6; ++n) { v[n] = A_param[tid * 6 + n]; mx = fmaxf(mx, v[n]); }
        float s = 0.f;
        #pragma unroll
        for (int n = 0; n < 6; ++n) { v[n] = expf(v[n] - mx); s += v[n]; }
        float inv = 1.f / s;
        #pragma unroll
        for (int n = 0; n < 6; ++n) g_A[tid * 8 + n] = v[n] * inv;
        g_A[tid * 8 + 6] = 0.f;
        g_A[tid * 8 + 7] = 0.f;
    }
    __syncthreads();

    // fill the cell table (integer compares against precomputed knot cells)
    for (int i = tid; i < NCELL; i += THREADS) {
        int n = 0, j = -1, cnt = 0;
        #pragma unroll
        for (int k = 0; k < 32; ++k) {
            int ck = kc[k];
            if (ck < i) ++n;
            else if (ck == i) { if (cnt == 0) j = k; ++cnt; }
        }
        float2 e;
        if (cnt == 0)      e = make_float2(aa[n], cc[n]);
        else if (cnt == 1) e = make_float2(__int_as_float(0x7FC00000), __uint_as_float((unsigned)j));
        else               e = make_float2(__int_as_float(0x7FC00000), __uint_as_float(64u));
        g_cell[i] = e;
    }
}

__global__ void __launch_bounds__(THREADS, 4) graphres_main(
    const float4* __restrict__ x,
    float4* __restrict__ out,
    int nvec4)
{
    __shared__ float2 sCell[NCELL];     // 16 KB, divergent LDS.64 resolve
    __shared__ float4 sKnot[32];        // knot-cell entries (few-lane path)
    __shared__ float  sSt[32], sdA[32]; // ultra-rare multi-knot fallback
    __shared__ float  sA[48];
    __shared__ float2 sBase;

    const int tid = threadIdx.x;

    // table copies: 2048 float2 = 1024 float4 -> 4 LDG.128/STS.128 per thread
    {
        const float4* src = (const float4*)g_cell;
        float4*       dst = (float4*)sCell;
        #pragma unroll
        for (int i = 0; i < 4; ++i) dst[tid + i * THREADS] = src[tid + i * THREADS];
    }
    if (tid < 48) sA[tid] = g_A[tid];
    if (tid < 32) {
        sKnot[tid] = g_knot[tid];
        sSt[tid]   = g_st[tid];
        sdA[tid]   = g_sdA[tid];
    }
    if (tid == 0) sBase = g_base;
    __syncthreads();

    const uint32_t aBase = (uint32_t)__cvta_generic_to_shared(sA);
    const uint32_t cBase = (uint32_t)__cvta_generic_to_shared(sCell);

    const int gt = blockIdx.x * THREADS + tid;
    const int b0 = gt * 3;                 // 3 float4 = 2 rows of 6
    if (b0 + 3 > nvec4) return;

    float4 v0 = x[b0 + 0];
    float4 v1 = x[b0 + 1];
    float4 v2 = x[b0 + 2];
    float xr[12] = { v0.x, v0.y, v0.z, v0.w,
                     v1.x, v1.y, v1.z, v1.w,
                     v2.x, v2.y, v2.z, v2.w };

    #pragma unroll
    for (int r = 0; r < 2; ++r) {
        float* xx = xr + r * 6;
        float yv[6];

        // matvec y = A @ x_row (A rows streamed from smem)
        #pragma unroll
        for (int m = 0; m < 6; ++m) {
            float a0, a1, a2, a3, a4, a5;
            uint32_t aaddr = aBase + (uint32_t)(m * 32);
            asm volatile("ld.shared.v4.f32 {%0,%1,%2,%3},[%4];"
                         : "=f"(a0), "=f"(a1), "=f"(a2), "=f"(a3) : "r"(aaddr));
            asm volatile("ld.shared.v2.f32 {%0,%1},[%2];"
                         : "=f"(a4), "=f"(a5) : "r"(aaddr + 16u));
            float pa = a0 * xx[0];
            float pb = a1 * xx[1];
            pa = fmaf(a2, xx[2], pa);
            pb = fmaf(a3, xx[3], pb);
            pa = fmaf(a4, xx[4], pa);
            pb = fmaf(a5, xx[5], pb);
            yv[m] = pa + pb;
        }

        // Phase 1: all 6 cell indices (independent ALU)
        uint32_t cadr[6];
        #pragma unroll
        for (int e = 0; e < 6; ++e)
            cadr[e] = cBase + ((uint32_t)cell_of(yv[e]) << 3);

        // Phase 2: all 6 divergent LDS.64 issued back-to-back (no branches
        // in between -> latencies overlap, MLP=6 instead of 1)
        float ca[6], cb[6];
        #pragma unroll
        for (int e = 0; e < 6; ++e)
            asm volatile("ld.shared.v2.f32 {%0,%1},[%2];"
                         : "=f"(ca[e]), "=f"(cb[e]) : "r"(cadr[e]));

        // Phase 3: evaluate; rare knot/multi-knot paths branch AFTER all
        // loads are already in flight
        #pragma unroll
        for (int e = 0; e < 6; ++e) {
            float y = yv[e];
            float fr = fmaf(ca[e], y, cb[e]);
            if (__builtin_expect(!(ca[e] == ca[e]), 0)) {
                unsigned j = __float_as_uint(cb[e]);
                if (j < 32u) {
                    float4 kn = sKnot[j];
                    fr = fmaf(kn.z, fmaxf(y - kn.w, 0.f), fmaf(kn.x, y, kn.y));
                } else {
                    float2 bs = sBase;
                    float acc = fmaf(bs.x, y, bs.y);
                    #pragma unroll 4
                    for (int k = 0; k < 32; ++k)
                        acc = fmaf(sdA[k], fmaxf(y - sSt[k], 0.f), acc);
                    fr = acc;
                }
            }
            xx[e] = fr + xx[e];
        }
    }

    out[b0 + 0] = make_float4(xr[0], xr[1], xr[2],  xr[3]);
    out[b0 + 1] = make_float4(xr[4], xr[5], xr[6],  xr[7]);
    out[b0 + 2] = make_float4(xr[8], xr[9], xr[10], xr[11]);
}

extern "C" void kernel_launch(void* const* d_in, const int* in_sizes, int n_in,
                              void* d_out, int out_size)
{
    const float* x  = (const float*)d_in[0];
    const float* Ap = (const float*)d_in[1];
    const float* W1 = (const float*)d_in[2];
    const float* b1 = (const float*)d_in[3];
    const float* W2 = (const float*)d_in[4];
    const float* b2 = (const float*)d_in[5];
    float* out = (float*)d_out;

    int nvec4 = out_size / 4;                       // total float4s (B*N/4)
    int threads_total = (nvec4 + 2) / 3;            // 3 float4 per thread
    int grid = (threads_total + THREADS - 1) / THREADS;

    setup_kernel<<<1, THREADS>>>(Ap, W1, b1, W2, b2);
    graphres_main<<<grid, THREADS>>>((const float4*)x, (float4*)out, nvec4);
}